// round 10
// baseline (speedup 1.0000x reference)
#include <cuda_runtime.h>

// ---------------------------------------------------------------------------
// MaskedAveragePooling, round 9:
//   1. scatter: bucket point indices per instance (atomic-return cursor =
//      count). No centroid atomics (R4 lesson).
//   2. pool: TWO 256-thread CTAs per instance (1024 CTAs -> 6.9 waves,
//      small tail; no launch_bounds cap -> no spills). Each CTA covers the
//      4 row-groups of its parity; unroll-8 float4 accumulation keeps 128B
//      in flight per thread. Per-half feature partials + centroid partials
//      to device scratch.
//   3. finalize: K CTAs x 64 thr combine the halves, write emb/centroid,
//      fused 3-layer MLP, then re-zero cursors (self-cleaning invariant).
// ---------------------------------------------------------------------------

#define PAD  32        // 128B stride between cursors -> spread over L2 slices
#define KMAX 1024
#define CAP  4096      // per-instance capacity (expected ~977, max ~1130)

__device__ int    g_cursor[KMAX * PAD];     // starts zeroed; finalize re-zeroes
__device__ int    g_plist[KMAX * CAP];
__device__ float4 g_part[2 * KMAX * 64];    // per-half feature partial sums
__device__ float  g_centp[2 * KMAX * 3];    // per-half centroid partial sums

// 4-way unrolled scatter: 4 independent atomic chains per thread.
__global__ void scatter_kernel(const int* __restrict__ ids, int N) {
    int T  = gridDim.x * blockDim.x;
    int i0 = blockIdx.x * blockDim.x + threadIdx.x;
    int id[4];
#pragma unroll
    for (int u = 0; u < 4; u++) {
        int j = i0 + u * T;
        id[u] = (j < N) ? ids[j] : -1;
    }
#pragma unroll
    for (int u = 0; u < 4; u++) {
        if (id[u] >= 0) {
            int pos = atomicAdd(&g_cursor[id[u] * PAD], 1);
            if (pos < CAP) g_plist[id[u] * CAP + pos] = i0 + u * T;
        }
    }
}

// blockIdx.x = 2k + h. 256 threads: c = tid&63 float4-column, this CTA owns
// row-groups {4h+0 .. 4h+3} of an 8-way interleave. Unroll 8 -> eight
// independent 16B loads in flight per thread.
__global__ void pool_kernel(
    const float4* __restrict__ feat4,   // [N, 64] float4
    const float*  __restrict__ coords)  // [N, 3]
{
    int k    = blockIdx.x >> 1;
    int h    = blockIdx.x & 1;
    int tid  = threadIdx.x;
    int c    = tid & 63;
    int r    = tid >> 6;          // 0..3
    int rg   = h * 4 + r;         // 0..7: this thread's row-group (stride 8)
    int lane = tid & 31;
    int wid  = tid >> 5;

    int cnt = g_cursor[k * PAD];
    int cl  = (cnt < CAP) ? cnt : CAP;
    const int* plist = g_plist + (size_t)k * CAP;

    // ---- feature partial: unroll-8, row stride 8 -> 64 rows per iter ----
    float4 acc = make_float4(0.f, 0.f, 0.f, 0.f);
    int p = rg;
    for (; p + 56 < cl; p += 64) {
        int j0 = plist[p];
        int j1 = plist[p + 8];
        int j2 = plist[p + 16];
        int j3 = plist[p + 24];
        int j4 = plist[p + 32];
        int j5 = plist[p + 40];
        int j6 = plist[p + 48];
        int j7 = plist[p + 56];
        float4 f0 = feat4[(size_t)j0 * 64 + c];
        float4 f1 = feat4[(size_t)j1 * 64 + c];
        float4 f2 = feat4[(size_t)j2 * 64 + c];
        float4 f3 = feat4[(size_t)j3 * 64 + c];
        float4 f4 = feat4[(size_t)j4 * 64 + c];
        float4 f5 = feat4[(size_t)j5 * 64 + c];
        float4 f6 = feat4[(size_t)j6 * 64 + c];
        float4 f7 = feat4[(size_t)j7 * 64 + c];
        acc.x += f0.x; acc.y += f0.y; acc.z += f0.z; acc.w += f0.w;
        acc.x += f1.x; acc.y += f1.y; acc.z += f1.z; acc.w += f1.w;
        acc.x += f2.x; acc.y += f2.y; acc.z += f2.z; acc.w += f2.w;
        acc.x += f3.x; acc.y += f3.y; acc.z += f3.z; acc.w += f3.w;
        acc.x += f4.x; acc.y += f4.y; acc.z += f4.z; acc.w += f4.w;
        acc.x += f5.x; acc.y += f5.y; acc.z += f5.z; acc.w += f5.w;
        acc.x += f6.x; acc.y += f6.y; acc.z += f6.z; acc.w += f6.w;
        acc.x += f7.x; acc.y += f7.y; acc.z += f7.z; acc.w += f7.w;
    }
    for (; p < cl; p += 8) {
        int j = plist[p];
        float4 f = feat4[(size_t)j * 64 + c];
        acc.x += f.x; acc.y += f.y; acc.z += f.z; acc.w += f.w;
    }

    __shared__ float4 s_part[256];
    __shared__ float  s_cw[8 * 3];
    s_part[tid] = acc;

    // ---- centroid partial: indices == h (mod 2), shuffle reduction ----
    float cx = 0.f, cy = 0.f, cz = 0.f;
    for (int q = 2 * tid + h; q < cl; q += 512) {
        int i = plist[q];
        cx += coords[(size_t)i * 3 + 0];
        cy += coords[(size_t)i * 3 + 1];
        cz += coords[(size_t)i * 3 + 2];
    }
#pragma unroll
    for (int off = 16; off > 0; off >>= 1) {
        cx += __shfl_down_sync(0xffffffffu, cx, off);
        cy += __shfl_down_sync(0xffffffffu, cy, off);
        cz += __shfl_down_sync(0xffffffffu, cz, off);
    }
    if (lane == 0) {
        s_cw[wid * 3 + 0] = cx;
        s_cw[wid * 3 + 1] = cy;
        s_cw[wid * 3 + 2] = cz;
    }
    __syncthreads();

    if (r == 0) {
        float4 a = s_part[c];
        float4 b = s_part[c + 64];
        float4 d = s_part[c + 128];
        float4 e = s_part[c + 192];
        float4 s;
        s.x = a.x + b.x + d.x + e.x;
        s.y = a.y + b.y + d.y + e.y;
        s.z = a.z + b.z + d.z + e.z;
        s.w = a.w + b.w + d.w + e.w;
        g_part[(size_t)blockIdx.x * 64 + c] = s;
    }
    if (tid < 3) {
        float s = s_cw[0 + tid] + s_cw[3 + tid] + s_cw[6 + tid] + s_cw[9 + tid]
                + s_cw[12 + tid] + s_cw[15 + tid] + s_cw[18 + tid] + s_cw[21 + tid];
        g_centp[(size_t)blockIdx.x * 3 + tid] = s;
    }
}

// One CTA (64 threads) per instance: combine halves, write outputs, fused
// MLP, restore zeroed-cursor invariant.
__global__ void finalize_kernel(
    const float* __restrict__ W1,      // [D, H]
    const float* __restrict__ W2,      // [H, H]
    const float* __restrict__ W3,      // [H, OUT]
    const float* __restrict__ b3,      // [OUT]
    float* __restrict__ out_emb,       // [K, D]
    float* __restrict__ out_cent,      // [K, 3]
    float* __restrict__ out_mlp,       // [K, OUT]
    int H, int OUTC)
{
    int k   = blockIdx.x;
    int tid = threadIdx.x;            // 0..63

    int   cnt = g_cursor[k * PAD];
    float inv = (cnt > 0) ? (1.0f / (float)cnt) : 1.0f;

    __shared__ float s_emb[256];
    __shared__ float s_h1[64];
    __shared__ float s_h2[64];

    float4 a = g_part[(size_t)(2 * k) * 64 + tid];
    float4 b = g_part[(size_t)(2 * k + 1) * 64 + tid];
    float4 e;
    e.x = (a.x + b.x) * inv;
    e.y = (a.y + b.y) * inv;
    e.z = (a.z + b.z) * inv;
    e.w = (a.w + b.w) * inv;
    ((float4*)s_emb)[tid] = e;
    ((float4*)out_emb)[(size_t)k * 64 + tid] = e;

    if (tid < 3) {
        float s = g_centp[(size_t)(2 * k) * 3 + tid]
                + g_centp[(size_t)(2 * k + 1) * 3 + tid];
        out_cent[(size_t)k * 3 + tid] = s * inv;
    }
    __syncthreads();

    // Linear(256,64) -> ReLU
    {
        float hsum = 0.f;
#pragma unroll 8
        for (int d = 0; d < 256; d++) hsum += s_emb[d] * W1[(size_t)d * H + tid];
        s_h1[tid] = fmaxf(hsum, 0.f);
    }
    __syncthreads();
    // Linear(64,64) -> ReLU
    {
        float hsum = 0.f;
#pragma unroll 8
        for (int d = 0; d < 64; d++) hsum += s_h1[d] * W2[(size_t)d * H + tid];
        s_h2[tid] = fmaxf(hsum, 0.f);
    }
    __syncthreads();
    // Linear(64,OUT) + b3
    if (tid < OUTC) {
        float o = b3[tid];
#pragma unroll 8
        for (int d = 0; d < 64; d++) o += s_h2[d] * W3[(size_t)d * OUTC + tid];
        out_mlp[(size_t)k * OUTC + tid] = o;
    }

    // ---- self-clean for the next replay ----
    if (tid == 0) g_cursor[k * PAD] = 0;
}

extern "C" void kernel_launch(void* const* d_in, const int* in_sizes, int n_in,
                              void* d_out, int out_size) {
    const float* feat   = (const float*)d_in[0];
    const float* coords = (const float*)d_in[1];
    const int*   ids    = (const int*)d_in[2];

    int wi = 3;
    if (n_in >= 8 && in_sizes[3] == 1) wi = 4;

    const float* W1 = (const float*)d_in[wi + 0];
    const float* W2 = (const float*)d_in[wi + 1];
    const float* W3 = (const float*)d_in[wi + 2];
    const float* b3 = (const float*)d_in[wi + 3];

    int N    = in_sizes[2];
    int D    = in_sizes[0] / N;            // 256
    int H    = in_sizes[wi] / D;           // 64
    int OUTC = in_sizes[wi + 3];           // 32
    int K    = out_size / (D + 3 + OUTC);  // 512

    float* out      = (float*)d_out;
    float* out_emb  = out;
    float* out_cent = out + (size_t)K * D;
    float* out_mlp  = out_cent + (size_t)K * 3;

    int sblocks = (N + 256 * 4 - 1) / (256 * 4);
    scatter_kernel<<<sblocks, 256>>>(ids, N);
    pool_kernel<<<2 * K, 256>>>((const float4*)feat, coords);
    finalize_kernel<<<K, 64>>>(W1, W2, W3, b3,
                               out_emb, out_cent, out_mlp, H, OUTC);
}

// round 15
// speedup vs baseline: 1.3636x; 1.3636x over previous
#include <cuda_runtime.h>

// ---------------------------------------------------------------------------
// MaskedAveragePooling, round 10 (R7 architecture + scatter occupancy fix +
// 4-way-parallel MLP layer 1):
//   1. scatter: bucket point indices per instance; atomic-return cursor =
//      count. Unroll 2 / 977 blocks -> 250k threads (2x in-flight chains).
//   2. pool+MLP: one 256-thread CTA per instance (whole grid co-resident).
//      Unroll-8 float4 register accumulation (128B in flight per thread),
//      warp-shuffle centroid reduction, fused MLP with layer 1 split
//      across all 256 threads. Self-cleans cursor (no zero kernel).
// ---------------------------------------------------------------------------

#define PAD  32        // 128B stride between cursors -> spread over L2 slices
#define KMAX 1024
#define CAP  4096      // per-instance capacity (expected ~977, max ~1130)

__device__ int g_cursor[KMAX * PAD];   // starts zeroed; pool re-zeroes
__device__ int g_plist[KMAX * CAP];

// Unroll-2 scatter: maximize thread count -> more atomic chains in flight.
__global__ void scatter_kernel(const int* __restrict__ ids, int N) {
    int T  = gridDim.x * blockDim.x;
    int i0 = blockIdx.x * blockDim.x + threadIdx.x;
    int j0 = i0;
    int j1 = i0 + T;
    int id0 = (j0 < N) ? ids[j0] : -1;
    int id1 = (j1 < N) ? ids[j1] : -1;
    if (id0 >= 0) {
        int pos = atomicAdd(&g_cursor[id0 * PAD], 1);
        if (pos < CAP) g_plist[id0 * CAP + pos] = j0;
    }
    if (id1 >= 0) {
        int pos = atomicAdd(&g_cursor[id1 * PAD], 1);
        if (pos < CAP) g_plist[id1 * CAP + pos] = j1;
    }
}

// One CTA (256 threads) per instance. c = tid&63 float4-column, r = tid>>6
// row-group. Unroll 8 -> eight independent 16B loads in flight per thread.
__global__ void pool_mlp_kernel(
    const float4* __restrict__ feat4,  // [N, 64] float4
    const float*  __restrict__ coords, // [N, 3]
    const float*  __restrict__ W1,     // [D, H]
    const float*  __restrict__ W2,     // [H, H]
    const float*  __restrict__ W3,     // [H, OUT]
    const float*  __restrict__ b3,     // [OUT]
    float* __restrict__ out_emb,       // [K, D]
    float* __restrict__ out_cent,      // [K, 3]
    float* __restrict__ out_mlp,       // [K, OUT]
    int H, int OUTC)
{
    int k    = blockIdx.x;
    int tid  = threadIdx.x;
    int c    = tid & 63;
    int r    = tid >> 6;
    int lane = tid & 31;
    int wid  = tid >> 5;

    int   cnt = g_cursor[k * PAD];
    float inv = (cnt > 0) ? (1.0f / (float)cnt) : 1.0f;
    int   cl  = (cnt < CAP) ? cnt : CAP;
    const int* plist = g_plist + (size_t)k * CAP;

    // ---- feature mean: unroll-8 float4 register accumulation ----
    float4 acc = make_float4(0.f, 0.f, 0.f, 0.f);
    int p = r;
    for (; p + 28 < cl; p += 32) {
        int j0 = plist[p];
        int j1 = plist[p + 4];
        int j2 = plist[p + 8];
        int j3 = plist[p + 12];
        int j4 = plist[p + 16];
        int j5 = plist[p + 20];
        int j6 = plist[p + 24];
        int j7 = plist[p + 28];
        float4 f0 = feat4[(size_t)j0 * 64 + c];
        float4 f1 = feat4[(size_t)j1 * 64 + c];
        float4 f2 = feat4[(size_t)j2 * 64 + c];
        float4 f3 = feat4[(size_t)j3 * 64 + c];
        float4 f4 = feat4[(size_t)j4 * 64 + c];
        float4 f5 = feat4[(size_t)j5 * 64 + c];
        float4 f6 = feat4[(size_t)j6 * 64 + c];
        float4 f7 = feat4[(size_t)j7 * 64 + c];
        acc.x += f0.x; acc.y += f0.y; acc.z += f0.z; acc.w += f0.w;
        acc.x += f1.x; acc.y += f1.y; acc.z += f1.z; acc.w += f1.w;
        acc.x += f2.x; acc.y += f2.y; acc.z += f2.z; acc.w += f2.w;
        acc.x += f3.x; acc.y += f3.y; acc.z += f3.z; acc.w += f3.w;
        acc.x += f4.x; acc.y += f4.y; acc.z += f4.z; acc.w += f4.w;
        acc.x += f5.x; acc.y += f5.y; acc.z += f5.z; acc.w += f5.w;
        acc.x += f6.x; acc.y += f6.y; acc.z += f6.z; acc.w += f6.w;
        acc.x += f7.x; acc.y += f7.y; acc.z += f7.z; acc.w += f7.w;
    }
    for (; p < cl; p += 4) {
        int j = plist[p];
        float4 f = feat4[(size_t)j * 64 + c];
        acc.x += f.x; acc.y += f.y; acc.z += f.z; acc.w += f.w;
    }

    __shared__ float4 s_part[256];
    __shared__ float  s_emb[256];
    __shared__ float  s_red[256];
    __shared__ float  s_cw[8 * 3];     // per-warp centroid partials
    __shared__ float  s_h1[64];
    __shared__ float  s_h2[64];

    s_part[tid] = acc;

    // ---- centroid: strided partials + warp-shuffle reduction ----
    float cx = 0.f, cy = 0.f, cz = 0.f;
    for (int q = tid; q < cl; q += 256) {
        int i = plist[q];
        cx += coords[(size_t)i * 3 + 0];
        cy += coords[(size_t)i * 3 + 1];
        cz += coords[(size_t)i * 3 + 2];
    }
#pragma unroll
    for (int off = 16; off > 0; off >>= 1) {
        cx += __shfl_down_sync(0xffffffffu, cx, off);
        cy += __shfl_down_sync(0xffffffffu, cy, off);
        cz += __shfl_down_sync(0xffffffffu, cz, off);
    }
    if (lane == 0) {
        s_cw[wid * 3 + 0] = cx;
        s_cw[wid * 3 + 1] = cy;
        s_cw[wid * 3 + 2] = cz;
    }
    __syncthreads();

    // combine the 4 row-group partials -> embedding
    if (r == 0) {
        float4 a = s_part[c];
        float4 b = s_part[c + 64];
        float4 d = s_part[c + 128];
        float4 e = s_part[c + 192];
        float4 emb;
        emb.x = (a.x + b.x + d.x + e.x) * inv;
        emb.y = (a.y + b.y + d.y + e.y) * inv;
        emb.z = (a.z + b.z + d.z + e.z) * inv;
        emb.w = (a.w + b.w + d.w + e.w) * inv;
        ((float4*)s_emb)[c] = emb;
        ((float4*)out_emb)[(size_t)k * 64 + c] = emb;
    }
    if (tid < 3) {
        float s = s_cw[0 + tid] + s_cw[3 + tid] + s_cw[6 + tid] + s_cw[9 + tid]
                + s_cw[12 + tid] + s_cw[15 + tid] + s_cw[18 + tid] + s_cw[21 + tid];
        out_cent[(size_t)k * 3 + tid] = s * inv;
    }
    __syncthreads();   // s_emb visible to all

    // ---- fused MLP ----
    // Layer 1: Linear(256,64)+ReLU, split across ALL 256 threads:
    // neuron n = tid&63, d-slice s = tid>>6 (64 d's each) -> 4x less latency.
    {
        int n = c;
        int d0 = r * 64;
        float hsum = 0.f;
#pragma unroll 8
        for (int d = d0; d < d0 + 64; d++)
            hsum += s_emb[d] * W1[(size_t)d * H + n];
        s_red[tid] = hsum;
    }
    __syncthreads();
    if (tid < H) {
        float hv = s_red[tid] + s_red[tid + 64] + s_red[tid + 128] + s_red[tid + 192];
        s_h1[tid] = fmaxf(hv, 0.f);
    }
    __syncthreads();
    // Layer 2: Linear(64,64)+ReLU
    if (tid < H) {
        float hsum = 0.f;
#pragma unroll 8
        for (int d = 0; d < 64; d++) hsum += s_h1[d] * W2[(size_t)d * H + tid];
        s_h2[tid] = fmaxf(hsum, 0.f);
    }
    __syncthreads();
    // Layer 3: Linear(64,OUT) + b3
    if (tid < OUTC) {
        float o = b3[tid];
#pragma unroll 8
        for (int d = 0; d < 64; d++) o += s_h2[d] * W3[(size_t)d * OUTC + tid];
        out_mlp[(size_t)k * OUTC + tid] = o;
    }

    // ---- self-clean for the next replay (replaces the zero kernel) ----
    if (tid == 0) g_cursor[k * PAD] = 0;
}

extern "C" void kernel_launch(void* const* d_in, const int* in_sizes, int n_in,
                              void* d_out, int out_size) {
    const float* feat   = (const float*)d_in[0];
    const float* coords = (const float*)d_in[1];
    const int*   ids    = (const int*)d_in[2];

    int wi = 3;
    if (n_in >= 8 && in_sizes[3] == 1) wi = 4;

    const float* W1 = (const float*)d_in[wi + 0];
    const float* W2 = (const float*)d_in[wi + 1];
    const float* W3 = (const float*)d_in[wi + 2];
    const float* b3 = (const float*)d_in[wi + 3];

    int N    = in_sizes[2];
    int D    = in_sizes[0] / N;            // 256
    int H    = in_sizes[wi] / D;           // 64
    int OUTC = in_sizes[wi + 3];           // 32
    int K    = out_size / (D + 3 + OUTC);  // 512
    (void)D;

    float* out      = (float*)d_out;
    float* out_emb  = out;
    float* out_cent = out + (size_t)K * (in_sizes[0] / N);
    float* out_mlp  = out_cent + (size_t)K * 3;

    int sblocks = (N + 256 * 2 - 1) / (256 * 2);
    scatter_kernel<<<sblocks, 256>>>(ids, N);
    pool_mlp_kernel<<<K, 256>>>((const float4*)feat, coords, W1, W2, W3, b3,
                                out_emb, out_cent, out_mlp, H, OUTC);
}